// round 16
// baseline (speedup 1.0000x reference)
#include <cuda_runtime.h>
#include <cuda_bf16.h>

// Problem constants
#define BATCH 32
#define CCH   16     // channels
#define HID   128    // hidden
#define PCH   48     // perception channels = 3*C
#define HH    256
#define WW    256
#define TILE  128    // pixels per CTA (x-direction)

// smem geometry
#define PS_SW 28     // words per pixel row: 24 data (48 bf16) + 4 pad; XOR-swizzled
#define UPD_S 19     // float [128][19] (odd stride -> conflict-free column reads)

// smem word offsets
#define OFF_WF 0         // 4096 words: W1 bf16 frags (3072) + W2 bf16 frags (1024)
#define OFF_B1 4096      // 128
#define OFF_B2 4224      // 16
#define OFF_NS 4240      // 128 (noise row)
#define OFF_PS 4368      // 128*28 = 3584 (Upd aliases this after compute)
#define SMEM_WORDS (OFF_PS + 128 * PS_SW)     // 7952
#define SMEM_BYTES (SMEM_WORDS * 4)           // 31808

// Pre-converted weights (written by prep kernel each launch; no allocation)
// layout W1 (words 0..3071):   i = (((kt*8+n2p)*8+gid)*4+tig)*4 + n2lo*2 + j
//   kt=0..2 (k16-tile), n2p=0..7 (n8-tile pair), n2=2*n2p+n2lo, j selects k-half
// layout W2 (words 3072..4095): r = ((kt*8+gid)*4+tig)*4 + j   (kt = k16-tile 0..7)
__device__ unsigned int g_wf[4096];

__device__ __forceinline__ unsigned int pack_bf16(float lo, float hi) {
    unsigned short l = __bfloat16_as_ushort(__float2bfloat16(lo));
    unsigned short h = __bfloat16_as_ushort(__float2bfloat16(hi));
    return (unsigned int)l | ((unsigned int)h << 16);
}

// ---- prep: convert weights into MMA-fragment-native bf16 layouts ----
__global__ void prep_weights(const float* __restrict__ w1,
                             const float* __restrict__ w2)
{
    int i = blockIdx.x * 256 + threadIdx.x;
    if (i < 3072) {
        int j    = i & 1;
        int n2lo = (i >> 1) & 1;
        int tig  = (i >> 2) & 3;
        int gid  = (i >> 4) & 7;
        int n2p  = (i >> 7) & 7;
        int kt   = i >> 10;                       // 0..2
        int n = (n2p * 2 + n2lo) * 8 + gid;       // hidden col 0..127
        int k = kt * 16 + 2 * tig + 8 * j;        // perception k 0..46 (even)
        g_wf[i] = pack_bf16(w1[n * PCH + k], w1[n * PCH + k + 1]);
    } else if (i < 4096) {
        int r   = i - 3072;
        int j   = r & 3;
        int tig = (r >> 2) & 3;
        int gid = (r >> 4) & 7;
        int kt  = r >> 7;                         // 0..7
        int kw  = kt * 8 + tig + ((j & 1) ? 4 : 0);   // bf16x2 word row = k/2
        int n   = gid + ((j & 2) ? 8 : 0);
        g_wf[i] = pack_bf16(w2[n * HID + 2 * kw], w2[n * HID + 2 * kw + 1]);
    }
}

extern __shared__ unsigned int smem_w[];

#define MMA_BF16(AC, A0, A1, A2, A3, B0, B1)                                  \
    asm volatile(                                                             \
        "mma.sync.aligned.m16n8k16.row.col.f32.bf16.bf16.f32 "                \
        "{%0,%1,%2,%3}, {%4,%5,%6,%7}, {%8,%9}, {%0,%1,%2,%3};"               \
        : "+f"((AC)[0]), "+f"((AC)[1]), "+f"((AC)[2]), "+f"((AC)[3])          \
        : "r"(A0), "r"(A1), "r"(A2), "r"(A3), "r"(B0), "r"(B1))

__global__ void __launch_bounds__(256, 3)
nca_fused_kernel(const float* __restrict__ grid,
                 const float* __restrict__ noise,
                 const float* __restrict__ b1,
                 const float* __restrict__ b2,
                 float* __restrict__ out)
{
    unsigned int* Wf  = smem_w + OFF_WF;
    float*        B1s = (float*)(smem_w + OFF_B1);
    float*        B2s = (float*)(smem_w + OFF_B2);
    float*        Ns  = (float*)(smem_w + OFF_NS);
    unsigned int* Ps  = smem_w + OFF_PS;
    float*        Upd = (float*)(smem_w + OFF_PS);   // aliases Ps (after sync)

    const int tid  = threadIdx.x;
    const int b    = blockIdx.z;
    const int y    = blockIdx.y;
    const int x0   = blockIdx.x * TILE;
    const int lane = tid & 31;

    // ---- Phase 0: stage weights (uint4), biases, noise row ----
    #pragma unroll
    for (int i = 0; i < 4; i++)
        ((uint4*)Wf)[tid + 256 * i] = ((const uint4*)g_wf)[tid + 256 * i];
    if (tid < HID)  B1s[tid] = b1[tid];
    if (tid < CCH)  B2s[tid] = b2[tid];
    if (tid < TILE) Ns[tid]  = noise[((size_t)b * HH + y) * WW + x0 + tid];

    // ---- Phase 1: perception -> Ps[pixel][48] (bf16, swizzled), keep centers ----
    float vcr[8];
    {
        const int ym = y - 1, yp = y + 1;
        const bool okm = (ym >= 0), okp = (yp < HH);
        #pragma unroll
        for (int i = 0; i < 8; i++) {
            int t = tid + 256 * i;          // 0..2047
            int c = t >> 7;                 // channel
            int x = t & 127;                // pixel in tile (lanes consecutive)
            int gx = x0 + x;
            const float* base = grid + (((size_t)b * CCH + c) * HH) * WW;
            const float* r0 = base + (size_t)ym * WW;
            const float* r1 = base + (size_t)y  * WW;
            const float* r2 = base + (size_t)yp * WW;

            float vm = okm ? __ldg(r0 + gx) : 0.f;
            float vc =       __ldg(r1 + gx);
            float vp = okp ? __ldg(r2 + gx) : 0.f;
            vcr[i] = vc;                    // reused in phase 4 (no grid re-read)

            float lm = __shfl_up_sync(0xffffffffu, vm, 1);
            float lc = __shfl_up_sync(0xffffffffu, vc, 1);
            float lp = __shfl_up_sync(0xffffffffu, vp, 1);
            float rm = __shfl_down_sync(0xffffffffu, vm, 1);
            float rc = __shfl_down_sync(0xffffffffu, vc, 1);
            float rp = __shfl_down_sync(0xffffffffu, vp, 1);
            if (lane == 0) {
                bool ok = (gx > 0);
                lm = (okm && ok) ? __ldg(r0 + gx - 1) : 0.f;
                lc =         ok  ? __ldg(r1 + gx - 1) : 0.f;
                lp = (okp && ok) ? __ldg(r2 + gx - 1) : 0.f;
            }
            if (lane == 31) {
                bool ok = (gx < WW - 1);
                rm = (okm && ok) ? __ldg(r0 + gx + 1) : 0.f;
                rc =         ok  ? __ldg(r1 + gx + 1) : 0.f;
                rp = (okp && ok) ? __ldg(r2 + gx + 1) : 0.f;
            }

            // sobel_x exactly as written in the reference (no flip):
            // [[1,0,1],[2,0,-2],[1,0,-1]]/8
            float sx = 0.125f * (lm + rm + 2.f * lc - 2.f * rc + lp - rp);
            float sy = 0.125f * (lm + 2.f * vm + rm - lp - 2.f * vp - rp);

            // bf16 stores, XOR-swizzled on word bits [0:2) by (x>>3)&3
            unsigned char* prow = (unsigned char*)Ps + x * (PS_SW * 4);
            int sw = ((x >> 3) & 3) << 2;
            *(__nv_bfloat16*)(prow + ((6 * c    ) ^ sw)) = __float2bfloat16(vc);
            *(__nv_bfloat16*)(prow + ((6 * c + 2) ^ sw)) = __float2bfloat16(sx);
            *(__nv_bfloat16*)(prow + ((6 * c + 4) ^ sw)) = __float2bfloat16(sy);
        }
    }
    __syncthreads();

    const int warp = tid >> 5;
    const int gid  = lane >> 2;
    const int tig  = lane & 3;
    const int m0   = warp * 16;
    const int s0   = (2 * warp) & 3;        // swizzle key for rows m0..m0+7
    const int s1   = (2 * warp + 1) & 3;    // rows m0+8..m0+15

    // ---- A fragments (bf16, K=48 = 3 k16-tiles), loaded ONCE for both halves ----
    unsigned int A[3][4];
    #pragma unroll
    for (int kt = 0; kt < 3; kt++) {
        A[kt][0] = Ps[(m0 + gid)     * PS_SW + ((kt * 8 + tig)     ^ s0)];
        A[kt][1] = Ps[(m0 + gid + 8) * PS_SW + ((kt * 8 + tig)     ^ s1)];
        A[kt][2] = Ps[(m0 + gid)     * PS_SW + ((kt * 8 + tig + 4) ^ s0)];
        A[kt][3] = Ps[(m0 + gid + 8) * PS_SW + ((kt * 8 + tig + 4) ^ s1)];
    }

    // ---- GEMM1 (bf16, N in halves) fused into GEMM2 (bf16) via registers ----
    float f2a[2][4];
    #pragma unroll
    for (int nt = 0; nt < 2; nt++)
        #pragma unroll
        for (int j = 0; j < 4; j++) f2a[nt][j] = 0.f;

    #pragma unroll
    for (int half = 0; half < 2; half++) {
        float acc[8][4];
        #pragma unroll
        for (int nt = 0; nt < 8; nt++)
            #pragma unroll
            for (int j = 0; j < 4; j++) acc[nt][j] = 0.f;

        #pragma unroll
        for (int kt = 0; kt < 3; kt++) {
            #pragma unroll
            for (int q = 0; q < 4; q++) {
                const int n2p = half * 4 + q;
                uint4 B = ((const uint4*)Wf)[((kt * 8 + n2p) * 8 + gid) * 4 + tig];
                MMA_BF16(acc[2*q],   A[kt][0], A[kt][1], A[kt][2], A[kt][3], B.x, B.y);
                MMA_BF16(acc[2*q+1], A[kt][0], A[kt][1], A[kt][2], A[kt][3], B.z, B.w);
            }
        }

        // bias + ReLU + pack -> GEMM2 A fragments straight from accumulators
        #pragma unroll
        for (int p = 0; p < 4; p++) {
            const int colbase = half * 64 + p * 16;
            const float b1a = B1s[colbase + 2 * tig];
            const float b1b = B1s[colbase + 2 * tig + 1];
            const float b1c = B1s[colbase + 8 + 2 * tig];
            const float b1d = B1s[colbase + 8 + 2 * tig + 1];

            unsigned int a0 = pack_bf16(fmaxf(acc[2*p][0] + b1a, 0.f),
                                        fmaxf(acc[2*p][1] + b1b, 0.f));
            unsigned int a1 = pack_bf16(fmaxf(acc[2*p][2] + b1a, 0.f),
                                        fmaxf(acc[2*p][3] + b1b, 0.f));
            unsigned int a2 = pack_bf16(fmaxf(acc[2*p+1][0] + b1c, 0.f),
                                        fmaxf(acc[2*p+1][1] + b1d, 0.f));
            unsigned int a3 = pack_bf16(fmaxf(acc[2*p+1][2] + b1c, 0.f),
                                        fmaxf(acc[2*p+1][3] + b1d, 0.f));

            const int ktg = half * 4 + p;    // GEMM2 k16-tile 0..7
            uint4 B2 = ((const uint4*)(Wf + 3072))[(ktg * 8 + gid) * 4 + tig];
            MMA_BF16(f2a[0], a0, a1, a2, a3, B2.x, B2.y);
            MMA_BF16(f2a[1], a0, a1, a2, a3, B2.z, B2.w);
        }
    }

    // all Ps reads done -> safe to overwrite region with Upd
    __syncthreads();

    #pragma unroll
    for (int nt = 0; nt < 2; nt++) {
        const int col = nt * 8 + 2 * tig;
        const float bb0 = B2s[col], bb1 = B2s[col + 1];
        Upd[(m0 + gid)     * UPD_S + col]     = f2a[nt][0] + bb0;
        Upd[(m0 + gid)     * UPD_S + col + 1] = f2a[nt][1] + bb1;
        Upd[(m0 + gid + 8) * UPD_S + col]     = f2a[nt][2] + bb0;
        Upd[(m0 + gid + 8) * UPD_S + col + 1] = f2a[nt][3] + bb1;
    }
    __syncthreads();

    // ---- Phase 4: mask + residual + clip (grid from registers, noise from smem) ----
    #pragma unroll
    for (int i = 0; i < 8; i++) {
        int t  = tid + 256 * i;
        int ch = t >> 7;
        int x  = t & 127;
        size_t gi = (((size_t)b * CCH + ch) * HH + y) * WW + x0 + x;
        float mk = (Ns[x] < 0.5f) ? 1.f : 0.f;
        float v  = vcr[i] + Upd[x * UPD_S + ch] * mk;
        v = fminf(fmaxf(v, -2.f), 2.f);
        out[gi] = v;
    }
}

extern "C" void kernel_launch(void* const* d_in, const int* in_sizes, int n_in,
                              void* d_out, int out_size) {
    const float* grid  = (const float*)d_in[0];
    const float* noise = (const float*)d_in[1];
    const float* w1    = (const float*)d_in[2];
    const float* b1    = (const float*)d_in[3];
    const float* w2    = (const float*)d_in[4];
    const float* b2    = (const float*)d_in[5];
    float* out = (float*)d_out;

    static bool attr_set = false;   // one-time attribute; identical work per call
    if (!attr_set) {
        cudaFuncSetAttribute(nca_fused_kernel,
                             cudaFuncAttributeMaxDynamicSharedMemorySize,
                             SMEM_BYTES);
        attr_set = true;
    }

    prep_weights<<<16, 256>>>(w1, w2);   // 4096 threads; same stream, runs first

    dim3 g(WW / TILE, HH, BATCH);        // (2, 256, 32)
    nca_fused_kernel<<<g, 256, SMEM_BYTES>>>(grid, noise, b1, b2, out);
}

// round 17
// speedup vs baseline: 1.0945x; 1.0945x over previous
#include <cuda_runtime.h>
#include <cuda_bf16.h>

// Problem constants
#define BATCH 32
#define CCH   16     // channels
#define HID   128    // hidden
#define PCH   48     // perception channels = 3*C
#define HH    256
#define WW    256
#define TILE  128    // pixels per CTA (x-direction)

// smem geometry (all conflict-free by construction, no swizzle ALU)
#define PT_S  136    // Ps transposed: [k=48][pixel], stride 136 words
                     //   STS: lanes=consecutive x -> consecutive words
                     //   A-frag LDS: bank = (tig*136 + gid)%32 = 8*tig+gid (0..31 perm)
#define UPD_T 132    // Upd transposed: [ch=16][pixel], stride 132 words
                     //   write bank = (col*132+gid)%32 = 8*tig+gid ; read = consecutive x

// smem word offsets
#define OFF_WF 0         // 7168 words: W1 tf32 frags (6144) + W2 bf16 frags (1024)
                         // (Upd [16][132] = 2112 words ALIASES this after GEMM)
#define OFF_B1 7168      // 128
#define OFF_B2 7296      // 16
#define OFF_NS 7312      // 128 (noise row)
#define OFF_PS 7440      // 48*136 = 6528 (raw fp32 perception, read as tf32)
#define SMEM_WORDS (OFF_PS + PCH * PT_S)      // 13968
#define SMEM_BYTES (SMEM_WORDS * 4)           // 55872

// Pre-converted weights (written by prep kernel each launch; no allocation)
// W1 (words 0..6143):  i = ((kt*8+nt2)*8+gid)*16 + tig*4 + j   kt=0..5 k8-tiles
//   k = kt*8 + tig + 4*(j&1),  n = nt2*16 + gid + 8*(j>>1), value = cvt.rna.tf32(w1[n][k])
// W2 (words 6144..7167): r = ((kt*8+gid)*4+tig)*4 + j          kt=0..7 k16-tiles
__device__ unsigned int g_wf[7168];

__device__ __forceinline__ unsigned int f2tf32(float f) {
    unsigned int u;
    asm("cvt.rna.tf32.f32 %0, %1;" : "=r"(u) : "f"(f));
    return u;
}

__device__ __forceinline__ unsigned int pack_bf16(float lo, float hi) {
    unsigned short l = __bfloat16_as_ushort(__float2bfloat16(lo));
    unsigned short h = __bfloat16_as_ushort(__float2bfloat16(hi));
    return (unsigned int)l | ((unsigned int)h << 16);
}

__global__ void prep_weights(const float* __restrict__ w1,
                             const float* __restrict__ w2)
{
    int i = blockIdx.x * 256 + threadIdx.x;
    if (i < 6144) {
        int j   = i & 3;
        int tig = (i >> 2) & 3;
        int gid = (i >> 4) & 7;
        int nt2 = (i >> 7) & 7;
        int kt  = i >> 10;                        // 0..5
        int k = kt * 8 + tig + ((j & 1) ? 4 : 0);
        int n = nt2 * 16 + gid + ((j & 2) ? 8 : 0);
        g_wf[i] = f2tf32(w1[n * PCH + k]);        // proper rounding, free here
    } else if (i < 7168) {
        int r   = i - 6144;
        int j   = r & 3;
        int tig = (r >> 2) & 3;
        int gid = (r >> 4) & 7;
        int kt  = r >> 7;                         // 0..7
        int kw  = kt * 8 + tig + ((j & 1) ? 4 : 0);   // bf16x2 word row = k/2
        int n   = gid + ((j & 2) ? 8 : 0);
        g_wf[i] = pack_bf16(w2[n * HID + 2 * kw], w2[n * HID + 2 * kw + 1]);
    }
}

extern __shared__ unsigned int smem_w[];

#define MMA_TF32(AC, A0, A1, A2, A3, B0, B1)                                  \
    asm volatile(                                                             \
        "mma.sync.aligned.m16n8k8.row.col.f32.tf32.tf32.f32 "                 \
        "{%0,%1,%2,%3}, {%4,%5,%6,%7}, {%8,%9}, {%0,%1,%2,%3};"               \
        : "+f"((AC)[0]), "+f"((AC)[1]), "+f"((AC)[2]), "+f"((AC)[3])          \
        : "r"(A0), "r"(A1), "r"(A2), "r"(A3), "r"(B0), "r"(B1))

#define MMA_BF16(AC, A0, A1, A2, A3, B0, B1)                                  \
    asm volatile(                                                             \
        "mma.sync.aligned.m16n8k16.row.col.f32.bf16.bf16.f32 "                \
        "{%0,%1,%2,%3}, {%4,%5,%6,%7}, {%8,%9}, {%0,%1,%2,%3};"               \
        : "+f"((AC)[0]), "+f"((AC)[1]), "+f"((AC)[2]), "+f"((AC)[3])          \
        : "r"(A0), "r"(A1), "r"(A2), "r"(A3), "r"(B0), "r"(B1))

__global__ void __launch_bounds__(256, 3)
nca_fused_kernel(const float* __restrict__ grid,
                 const float* __restrict__ noise,
                 const float* __restrict__ b1,
                 const float* __restrict__ b2,
                 float* __restrict__ out)
{
    unsigned int* Wf  = smem_w + OFF_WF;
    float*        B1s = (float*)(smem_w + OFF_B1);
    float*        B2s = (float*)(smem_w + OFF_B2);
    float*        Ns  = (float*)(smem_w + OFF_NS);
    float*        PsF = (float*)(smem_w + OFF_PS);       // raw fp32, HW-tf32 on read
    unsigned int* Psu = smem_w + OFF_PS;
    float*        Upd = (float*)(smem_w + OFF_WF);       // aliases Wf (dead post-GEMM)

    const int tid  = threadIdx.x;
    const int b    = blockIdx.z;
    const int y    = blockIdx.y;
    const int x0   = blockIdx.x * TILE;
    const int lane = tid & 31;

    // ---- Phase 0: stage weights (uint4), biases, noise row ----
    #pragma unroll
    for (int i = 0; i < 7; i++)
        ((uint4*)Wf)[tid + 256 * i] = ((const uint4*)g_wf)[tid + 256 * i];
    if (tid < HID)  B1s[tid] = b1[tid];
    if (tid < CCH)  B2s[tid] = b2[tid];
    if (tid < TILE) Ns[tid]  = noise[((size_t)b * HH + y) * WW + x0 + tid];

    // ---- Phase 1: perception -> PsF[k][pixel] (fp32), 4-shuffle stencil ----
    {
        const int x  = tid & 127;           // fixed per thread
        const int c0 = tid >> 7;            // 0 or 1; c = c0 + 2*i
        const int gx = x0 + x;
        const int ym = y - 1, yp = y + 1;
        const bool okm = (ym >= 0), okp = (yp < HH);
        const bool xok_l = (gx > 0), xok_r = (gx < WW - 1);

        #pragma unroll
        for (int i = 0; i < 8; i++) {
            const int c = c0 + 2 * i;
            const float* base = grid + (((size_t)b * CCH + c) * HH) * WW;
            const float* r0 = base + (size_t)ym * WW;
            const float* r1 = base + (size_t)y  * WW;
            const float* r2 = base + (size_t)yp * WW;

            float vm = okm ? __ldg(r0 + gx) : 0.f;
            float vc =       __ldg(r1 + gx);
            float vp = okp ? __ldg(r2 + gx) : 0.f;

            // combined stencil terms: 4 shuffles instead of 6
            float L  = vm + 2.f * vc + vp;      // left-neighbor bundle for sx
            float Rn = vm - 2.f * vc - vp;      // right-neighbor bundle for sx
            float D  = vm - vp;                 // bundle for sy

            float upL = __shfl_up_sync(0xffffffffu, L, 1);
            float upD = __shfl_up_sync(0xffffffffu, D, 1);
            float dnR = __shfl_down_sync(0xffffffffu, Rn, 1);
            float dnD = __shfl_down_sync(0xffffffffu, D, 1);

            if (lane == 0) {   // true left neighbor (cross-warp / tile edge)
                float am = 0.f, ac = 0.f, ap = 0.f;
                if (xok_l) {
                    am = okm ? __ldg(r0 + gx - 1) : 0.f;
                    ac =       __ldg(r1 + gx - 1);
                    ap = okp ? __ldg(r2 + gx - 1) : 0.f;
                }
                upL = am + 2.f * ac + ap;
                upD = am - ap;
            }
            if (lane == 31) {  // true right neighbor
                float bm = 0.f, bc = 0.f, bp = 0.f;
                if (xok_r) {
                    bm = okm ? __ldg(r0 + gx + 1) : 0.f;
                    bc =       __ldg(r1 + gx + 1);
                    bp = okp ? __ldg(r2 + gx + 1) : 0.f;
                }
                dnR = bm - 2.f * bc - bp;
                dnD = bm - bp;
            }

            // sobel_x exactly as written in the reference (no flip):
            // [[1,0,1],[2,0,-2],[1,0,-1]]/8 ; sobel_y [[1,2,1],[0,0,0],[-1,-2,-1]]/8
            float sx = 0.125f * (upL + dnR);
            float sy = 0.125f * (upD + 2.f * D + dnD);

            // transposed, conflict-free, zero address trickery
            PsF[(3 * c    ) * PT_S + x] = vc;
            PsF[(3 * c + 1) * PT_S + x] = sx;
            PsF[(3 * c + 2) * PT_S + x] = sy;
        }
    }
    __syncthreads();

    const int warp = tid >> 5;
    const int gid  = lane >> 2;
    const int tig  = lane & 3;
    const int m0   = warp * 16;

    // ---- A fragments (tf32, K=48 = 6 k8-tiles), loaded ONCE for both halves ----
    unsigned int A[6][4];
    #pragma unroll
    for (int kt = 0; kt < 6; kt++) {
        const int k0 = kt * 8;
        A[kt][0] = Psu[(k0 + tig)     * PT_S + m0 + gid];
        A[kt][1] = Psu[(k0 + tig)     * PT_S + m0 + gid + 8];
        A[kt][2] = Psu[(k0 + tig + 4) * PT_S + m0 + gid];
        A[kt][3] = Psu[(k0 + tig + 4) * PT_S + m0 + gid + 8];
    }

    // ---- GEMM1 (tf32, N in halves) fused into GEMM2 (bf16) via registers ----
    float f2a[2][4];
    #pragma unroll
    for (int nt = 0; nt < 2; nt++)
        #pragma unroll
        for (int j = 0; j < 4; j++) f2a[nt][j] = 0.f;

    #pragma unroll
    for (int half = 0; half < 2; half++) {
        float acc[8][4];
        #pragma unroll
        for (int nt = 0; nt < 8; nt++)
            #pragma unroll
            for (int j = 0; j < 4; j++) acc[nt][j] = 0.f;

        #pragma unroll
        for (int kt = 0; kt < 6; kt++) {
            #pragma unroll
            for (int q = 0; q < 4; q++) {
                const int n2p = half * 4 + q;
                uint4 B = ((const uint4*)Wf)[((kt * 8 + n2p) * 8 + gid) * 4 + tig];
                MMA_TF32(acc[2*q],   A[kt][0], A[kt][1], A[kt][2], A[kt][3], B.x, B.y);
                MMA_TF32(acc[2*q+1], A[kt][0], A[kt][1], A[kt][2], A[kt][3], B.z, B.w);
            }
        }

        // bias + ReLU + pack -> GEMM2 A fragments straight from accumulators
        #pragma unroll
        for (int p = 0; p < 4; p++) {
            const int colbase = half * 64 + p * 16;
            const float b1a = B1s[colbase + 2 * tig];
            const float b1b = B1s[colbase + 2 * tig + 1];
            const float b1c = B1s[colbase + 8 + 2 * tig];
            const float b1d = B1s[colbase + 8 + 2 * tig + 1];

            unsigned int a0 = pack_bf16(fmaxf(acc[2*p][0] + b1a, 0.f),
                                        fmaxf(acc[2*p][1] + b1b, 0.f));
            unsigned int a1 = pack_bf16(fmaxf(acc[2*p][2] + b1a, 0.f),
                                        fmaxf(acc[2*p][3] + b1b, 0.f));
            unsigned int a2 = pack_bf16(fmaxf(acc[2*p+1][0] + b1c, 0.f),
                                        fmaxf(acc[2*p+1][1] + b1d, 0.f));
            unsigned int a3 = pack_bf16(fmaxf(acc[2*p+1][2] + b1c, 0.f),
                                        fmaxf(acc[2*p+1][3] + b1d, 0.f));

            const int ktg = half * 4 + p;    // GEMM2 k16-tile 0..7
            uint4 B2 = ((const uint4*)(Wf + 6144))[(ktg * 8 + gid) * 4 + tig];
            MMA_BF16(f2a[0], a0, a1, a2, a3, B2.x, B2.y);
            MMA_BF16(f2a[1], a0, a1, a2, a3, B2.z, B2.w);
        }
    }

    // all Wf reads done across the CTA -> safe to overwrite Wf region with Upd
    __syncthreads();

    #pragma unroll
    for (int nt = 0; nt < 2; nt++) {
        const int col = nt * 8 + 2 * tig;
        const float bb0 = B2s[col], bb1 = B2s[col + 1];
        Upd[ col      * UPD_T + m0 + gid]     = f2a[nt][0] + bb0;
        Upd[(col + 1) * UPD_T + m0 + gid]     = f2a[nt][1] + bb1;
        Upd[ col      * UPD_T + m0 + gid + 8] = f2a[nt][2] + bb0;
        Upd[(col + 1) * UPD_T + m0 + gid + 8] = f2a[nt][3] + bb1;
    }
    __syncthreads();

    // ---- Phase 4: mask + residual + clip (centers from Ps, noise from smem) ----
    {
        const int x  = tid & 127;
        const int c0 = tid >> 7;
        const float mk = (Ns[x] < 0.5f) ? 1.f : 0.f;
        #pragma unroll
        for (int i = 0; i < 8; i++) {
            const int ch = c0 + 2 * i;
            size_t gi = (((size_t)b * CCH + ch) * HH + y) * WW + x0 + x;
            float g = PsF[(3 * ch) * PT_S + x];         // identity row = center value
            float v = g + Upd[ch * UPD_T + x] * mk;
            v = fminf(fmaxf(v, -2.f), 2.f);
            out[gi] = v;
        }
    }
}

extern "C" void kernel_launch(void* const* d_in, const int* in_sizes, int n_in,
                              void* d_out, int out_size) {
    const float* grid  = (const float*)d_in[0];
    const float* noise = (const float*)d_in[1];
    const float* w1    = (const float*)d_in[2];
    const float* b1    = (const float*)d_in[3];
    const float* w2    = (const float*)d_in[4];
    const float* b2    = (const float*)d_in[5];
    float* out = (float*)d_out;

    static bool attr_set = false;   // one-time attribute; identical work per call
    if (!attr_set) {
        cudaFuncSetAttribute(nca_fused_kernel,
                             cudaFuncAttributeMaxDynamicSharedMemorySize,
                             SMEM_BYTES);
        attr_set = true;
    }

    prep_weights<<<28, 256>>>(w1, w2);   // 7168 threads; same stream, runs first

    dim3 g(WW / TILE, HH, BATCH);        // (2, 256, 32)
    nca_fused_kernel<<<g, 256, SMEM_BYTES>>>(grid, noise, b1, b2, out);
}